// round 3
// baseline (speedup 1.0000x reference)
#include <cuda_runtime.h>
#include <cuda_bf16.h>
#include <stdint.h>

#define N_NODES 50000
#define N_EDGES 50000
#define IN_C 256
#define HID_C 128
#define OUT_C 64

// ---------------- scratch (no allocations allowed) ----------------
__device__ float g_h0[(size_t)N_NODES * HID_C];   // x @ W1
__device__ float g_m [(size_t)N_EDGES * HID_C];   // edge aggregation buffer (reused at C=64)
__device__ float g_h1[(size_t)N_NODES * OUT_C];   // f1 @ W2
__device__ float g_dinv[N_NODES];                 // node degree -> 1/deg
__device__ float g_binv[N_EDGES];                 // edge size  -> 1/size

// ---------------- degree kernels ----------------
__global__ void count_deg_kernel(const int* __restrict__ node_idx,
                                 const int* __restrict__ edge_idx,
                                 float* __restrict__ dcnt, float* __restrict__ bcnt,
                                 int nnz) {
    int t = blockIdx.x * blockDim.x + threadIdx.x;
    if (t < nnz) {
        atomicAdd(&dcnt[node_idx[t]], 1.0f);
        atomicAdd(&bcnt[edge_idx[t]], 1.0f);
    }
}

__global__ void invert_kernel(float* __restrict__ p, int n) {
    int t = blockIdx.x * blockDim.x + threadIdx.x;
    if (t < n) {
        float v = p[t];
        p[t] = (v > 0.0f) ? (1.0f / v) : 0.0f;
    }
}

// ---------------- tiled fp32 GEMM: C = A[M,K] @ B[K,N] (+bias) ----------------
// BM=64, BN=64, BK=16, 256 threads, 4x4 microtile.
// N and K are multiples of 64/16 in this problem; only M needs bounds checks.
__global__ void sgemm_kernel(const float* __restrict__ A, const float* __restrict__ B,
                             float* __restrict__ C, int M, int N, int K,
                             const float* __restrict__ bias) {
    const int BM = 64, BN = 64, BK = 16;
    __shared__ float As[BK][BM + 1];
    __shared__ float Bs[BK][BN];

    int tid = threadIdx.x;
    int tr = tid / 16;   // 0..15
    int tc = tid % 16;   // 0..15
    int rowBase = blockIdx.x * BM;
    int colBase = blockIdx.y * BN;

    float acc[4][4] = {};

    for (int k0 = 0; k0 < K; k0 += BK) {
        // A tile (64x16), stored transposed
        #pragma unroll
        for (int i = 0; i < 4; i++) {
            int linear = tid + i * 256;          // 0..1023
            int r = linear / BK;
            int c = linear % BK;
            int gr = rowBase + r;
            As[c][r] = (gr < M) ? A[(size_t)gr * K + k0 + c] : 0.0f;
        }
        // B tile (16x64)
        #pragma unroll
        for (int i = 0; i < 4; i++) {
            int linear = tid + i * 256;
            int r = linear / BN;
            int c = linear % BN;
            Bs[r][c] = B[(size_t)(k0 + r) * N + colBase + c];
        }
        __syncthreads();

        #pragma unroll
        for (int kk = 0; kk < BK; kk++) {
            float a[4], b[4];
            #pragma unroll
            for (int i = 0; i < 4; i++) a[i] = As[kk][tr * 4 + i];
            #pragma unroll
            for (int j = 0; j < 4; j++) b[j] = Bs[kk][tc * 4 + j];
            #pragma unroll
            for (int i = 0; i < 4; i++)
                #pragma unroll
                for (int j = 0; j < 4; j++)
                    acc[i][j] += a[i] * b[j];
        }
        __syncthreads();
    }

    #pragma unroll
    for (int i = 0; i < 4; i++) {
        int gr = rowBase + tr * 4 + i;
        if (gr >= M) continue;
        #pragma unroll
        for (int j = 0; j < 4; j++) {
            int gc = colBase + tc * 4 + j;
            float v = acc[i][j];
            if (bias) v += bias[gc];
            C[(size_t)gr * N + gc] = v;
        }
    }
}

// ---------------- gather + atomic scatter-add ----------------
// dst[sidx[e]] += src[gidx[e]] * (scale ? scale[gidx[e]] : 1)
// One thread handles 4 channels (float4 gather, 4 scalar atomics).
template <int C4>
__global__ void gather_scatter_kernel(const float4* __restrict__ src,
                                      const int* __restrict__ gidx,
                                      const int* __restrict__ sidx,
                                      const float* __restrict__ scale,
                                      float* __restrict__ dst, int nnz) {
    int t = blockIdx.x * blockDim.x + threadIdx.x;
    int e = t / C4;
    int q = t % C4;
    if (e >= nnz) return;
    int s = gidx[e];
    int d = sidx[e];
    float4 v = src[(size_t)s * C4 + q];
    float sc = scale ? scale[s] : 1.0f;
    float* dp = dst + ((size_t)d * C4 + q) * 4;
    atomicAdd(dp + 0, v.x * sc);
    atomicAdd(dp + 1, v.y * sc);
    atomicAdd(dp + 2, v.z * sc);
    atomicAdd(dp + 3, v.w * sc);
}

// ---------------- finalize: out = relu(out * dinv[row] + bias[col]) ----------------
__global__ void finalize_kernel(float* __restrict__ out, const float* __restrict__ dinv,
                                const float* __restrict__ bias, int rows, int C) {
    int t = blockIdx.x * blockDim.x + threadIdx.x;
    if (t >= rows * C) return;
    int row = t / C;
    int c = t % C;
    float v = out[t] * dinv[row] + bias[c];
    out[t] = fmaxf(v, 0.0f);
}

// ---------------- launch ----------------
extern "C" void kernel_launch(void* const* d_in, const int* in_sizes, int n_in,
                              void* d_out, int out_size) {
    const float* x    = (const float*)d_in[0];
    const int*   hidx = (const int*)d_in[1];   // JAX x64 disabled -> int32
    const float* W1   = (const float*)d_in[2];
    const float* b1   = (const float*)d_in[3];
    const float* W2   = (const float*)d_in[4];
    const float* b2   = (const float*)d_in[5];
    const float* Wp   = (const float*)d_in[6];
    const float* bp   = (const float*)d_in[7];

    int nnz = in_sizes[1] / 2;
    const int* node_idx = hidx;
    const int* edge_idx = hidx + nnz;

    // output layout: (z [N,64], features_1 [N,128], features_2 [N,64])
    float* z  = (float*)d_out;
    float* f1 = z  + (size_t)N_NODES * OUT_C;
    float* f2 = f1 + (size_t)N_NODES * HID_C;

    float *p_h0, *p_m, *p_h1, *p_dinv, *p_binv;
    cudaGetSymbolAddress((void**)&p_h0,   g_h0);
    cudaGetSymbolAddress((void**)&p_m,    g_m);
    cudaGetSymbolAddress((void**)&p_h1,   g_h1);
    cudaGetSymbolAddress((void**)&p_dinv, g_dinv);
    cudaGetSymbolAddress((void**)&p_binv, g_binv);

    // ---- degrees ----
    cudaMemsetAsync(p_dinv, 0, N_NODES * sizeof(float));
    cudaMemsetAsync(p_binv, 0, N_EDGES * sizeof(float));
    count_deg_kernel<<<(nnz + 255) / 256, 256>>>(node_idx, edge_idx, p_dinv, p_binv, nnz);
    invert_kernel<<<(N_NODES + 255) / 256, 256>>>(p_dinv, N_NODES);
    invert_kernel<<<(N_EDGES + 255) / 256, 256>>>(p_binv, N_EDGES);

    // ---- layer 1: h0 = x @ W1 ----
    {
        dim3 grid((N_NODES + 63) / 64, HID_C / 64);
        sgemm_kernel<<<grid, 256>>>(x, W1, p_h0, N_NODES, HID_C, IN_C, nullptr);
    }
    // edge aggregation then node aggregation (C=128)
    cudaMemsetAsync(p_m, 0, (size_t)N_EDGES * HID_C * sizeof(float));
    cudaMemsetAsync(f1,  0, (size_t)N_NODES * HID_C * sizeof(float));
    {
        const int C4 = HID_C / 4;
        long long total = (long long)nnz * C4;
        int blocks = (int)((total + 255) / 256);
        gather_scatter_kernel<C4><<<blocks, 256>>>((const float4*)p_h0, node_idx, edge_idx,
                                                   nullptr, p_m, nnz);
        gather_scatter_kernel<C4><<<blocks, 256>>>((const float4*)p_m, edge_idx, node_idx,
                                                   p_binv, f1, nnz);
    }
    finalize_kernel<<<(N_NODES * HID_C + 255) / 256, 256>>>(f1, p_dinv, b1, N_NODES, HID_C);

    // ---- layer 2: h1 = f1 @ W2 ----
    {
        dim3 grid((N_NODES + 63) / 64, OUT_C / 64);
        sgemm_kernel<<<grid, 256>>>(f1, W2, p_h1, N_NODES, OUT_C, HID_C, nullptr);
    }
    cudaMemsetAsync(p_m, 0, (size_t)N_EDGES * OUT_C * sizeof(float));
    cudaMemsetAsync(f2,  0, (size_t)N_NODES * OUT_C * sizeof(float));
    {
        const int C4 = OUT_C / 4;
        long long total = (long long)nnz * C4;
        int blocks = (int)((total + 255) / 256);
        gather_scatter_kernel<C4><<<blocks, 256>>>((const float4*)p_h1, node_idx, edge_idx,
                                                   nullptr, p_m, nnz);
        gather_scatter_kernel<C4><<<blocks, 256>>>((const float4*)p_m, edge_idx, node_idx,
                                                   p_binv, f2, nnz);
    }
    finalize_kernel<<<(N_NODES * OUT_C + 255) / 256, 256>>>(f2, p_dinv, b2, N_NODES, OUT_C);

    // ---- projection: z = f2 @ Wp + bp ----
    {
        dim3 grid((N_NODES + 63) / 64, OUT_C / 64);
        sgemm_kernel<<<grid, 256>>>(f2, Wp, z, N_NODES, OUT_C, OUT_C, bp);
    }
}

// round 4
// speedup vs baseline: 2.4927x; 2.4927x over previous
#include <cuda_runtime.h>
#include <cuda_bf16.h>
#include <stdint.h>

#define N_NODES 50000
#define N_EDGES 50000
#define IN_C 256
#define HID_C 128
#define OUT_C 64
#define MAX_NNZ 800000

// ---------------- scratch (no allocations allowed) ----------------
__device__ float g_h0[(size_t)N_NODES * HID_C];   // x @ W1
__device__ float g_m [(size_t)N_EDGES * HID_C];   // edge aggregation buffer (reused at C=64)
__device__ float g_h1[(size_t)N_NODES * OUT_C];   // f1 @ W2
__device__ float g_dinv[N_NODES];
__device__ float g_binv[N_EDGES];

__device__ int g_ecnt[N_EDGES];
__device__ int g_ncnt[N_NODES];
__device__ int g_eoff[N_EDGES + 1];
__device__ int g_noff[N_NODES + 1];
__device__ int g_ecur[N_EDGES];
__device__ int g_ncur[N_NODES];
__device__ int g_eadj[MAX_NNZ];   // per edge-row: node indices
__device__ int g_nadj[MAX_NNZ];   // per node-row: edge indices

// ---------------- histogram ----------------
__global__ void hist_kernel(const int* __restrict__ node_idx,
                            const int* __restrict__ edge_idx,
                            int* __restrict__ ncnt, int* __restrict__ ecnt, int nnz) {
    int t = blockIdx.x * blockDim.x + threadIdx.x;
    if (t < nnz) {
        atomicAdd(&ncnt[node_idx[t]], 1);
        atomicAdd(&ecnt[edge_idx[t]], 1);
    }
}

// ---------------- exclusive scan over 50k ints, one block per array ----------------
__global__ void scan_kernel(const int* __restrict__ cntE, int* __restrict__ offE,
                            const int* __restrict__ cntN, int* __restrict__ offN, int n) {
    const int* cnt = (blockIdx.x == 0) ? cntE : cntN;
    int* off       = (blockIdx.x == 0) ? offE : offN;
    __shared__ int sh[1024];
    int tid = threadIdx.x;
    int chunk = (n + 1023) / 1024;
    int start = tid * chunk;
    int end = min(start + chunk, n);
    int s = 0;
    for (int i = start; i < end; i++) s += cnt[i];
    sh[tid] = s;
    __syncthreads();
    // Hillis-Steele inclusive scan
    for (int d = 1; d < 1024; d <<= 1) {
        int v = (tid >= d) ? sh[tid - d] : 0;
        __syncthreads();
        sh[tid] += v;
        __syncthreads();
    }
    int run = (tid == 0) ? 0 : sh[tid - 1];
    for (int i = start; i < end; i++) {
        off[i] = run;
        run += cnt[i];
    }
    if (tid == 1023) off[n] = sh[1023];
}

// ---------------- 1/count ----------------
__global__ void invert_cnt_kernel(const int* __restrict__ ncnt, float* __restrict__ dinv,
                                  const int* __restrict__ ecnt, float* __restrict__ binv, int n) {
    int t = blockIdx.x * blockDim.x + threadIdx.x;
    if (t < n) {
        int c0 = ncnt[t];
        dinv[t] = (c0 > 0) ? (1.0f / (float)c0) : 0.0f;
        int c1 = ecnt[t];
        binv[t] = (c1 > 0) ? (1.0f / (float)c1) : 0.0f;
    }
}

// ---------------- CSR fill ----------------
__global__ void fill_kernel(const int* __restrict__ node_idx, const int* __restrict__ edge_idx,
                            const int* __restrict__ eoff, const int* __restrict__ noff,
                            int* __restrict__ ecur, int* __restrict__ ncur,
                            int* __restrict__ eadj, int* __restrict__ nadj, int nnz) {
    int t = blockIdx.x * blockDim.x + threadIdx.x;
    if (t < nnz) {
        int nd = node_idx[t];
        int eg = edge_idx[t];
        int p = atomicAdd(&ecur[eg], 1);
        eadj[eoff[eg] + p] = nd;
        int q = atomicAdd(&ncur[nd], 1);
        nadj[noff[nd] + q] = eg;
    }
}

// ---------------- warp-per-row gather-reduce ----------------
// out[row] = (sum over nb in adj[off[row]..off[row+1]) of src[nb] * (SRC_SCALE? sscale[nb]:1))
//            then if FINAL: * rscale[row] + bias, relu.
// C = 32*VEC channels; lane covers channels [lane*VEC, lane*VEC+VEC).
template <int VEC, bool SRC_SCALE, bool FINAL>
__global__ void agg_kernel(const float* __restrict__ src, const int* __restrict__ adj,
                           const int* __restrict__ off, const float* __restrict__ sscale,
                           float* __restrict__ out, const float* __restrict__ rscale,
                           const float* __restrict__ bias, int rows) {
    int warp = (blockIdx.x * blockDim.x + threadIdx.x) >> 5;
    int lane = threadIdx.x & 31;
    if (warp >= rows) return;
    const int C = 32 * VEC;
    int s0 = off[warp];
    int s1 = off[warp + 1];

    float acc[VEC];
#pragma unroll
    for (int k = 0; k < VEC; k++) acc[k] = 0.0f;

    for (int j = s0; j < s1; j++) {
        int nb = adj[j];
        float sc = SRC_SCALE ? sscale[nb] : 1.0f;
        const float* p = src + (size_t)nb * C + lane * VEC;
        if (VEC == 4) {
            float4 v = *reinterpret_cast<const float4*>(p);
            acc[0] += v.x * sc; acc[1] += v.y * sc;
            acc[2] += v.z * sc; acc[3] += v.w * sc;
        } else {
            float2 v = *reinterpret_cast<const float2*>(p);
            acc[0] += v.x * sc; acc[1] += v.y * sc;
        }
    }

    float* q = out + (size_t)warp * C + lane * VEC;
    if (FINAL) {
        float rs = rscale[warp];
#pragma unroll
        for (int k = 0; k < VEC; k++)
            acc[k] = fmaxf(acc[k] * rs + bias[lane * VEC + k], 0.0f);
    }
    if (VEC == 4) {
        *reinterpret_cast<float4*>(q) = make_float4(acc[0], acc[1], acc[2], acc[3]);
    } else {
        *reinterpret_cast<float2*>(q) = make_float2(acc[0], acc[1]);
    }
}

// ---------------- tiled fp32 GEMM: C = A[M,K] @ B[K,N] (+bias) ----------------
__global__ void sgemm_kernel(const float* __restrict__ A, const float* __restrict__ B,
                             float* __restrict__ C, int M, int N, int K,
                             const float* __restrict__ bias) {
    const int BM = 64, BN = 64, BK = 16;
    __shared__ float As[BK][BM + 1];
    __shared__ float Bs[BK][BN];

    int tid = threadIdx.x;
    int tr = tid / 16;
    int tc = tid % 16;
    int rowBase = blockIdx.x * BM;
    int colBase = blockIdx.y * BN;

    float acc[4][4] = {};

    for (int k0 = 0; k0 < K; k0 += BK) {
#pragma unroll
        for (int i = 0; i < 4; i++) {
            int linear = tid + i * 256;
            int r = linear / BK;
            int c = linear % BK;
            int gr = rowBase + r;
            As[c][r] = (gr < M) ? A[(size_t)gr * K + k0 + c] : 0.0f;
        }
#pragma unroll
        for (int i = 0; i < 4; i++) {
            int linear = tid + i * 256;
            int r = linear / BN;
            int c = linear % BN;
            Bs[r][c] = B[(size_t)(k0 + r) * N + colBase + c];
        }
        __syncthreads();

#pragma unroll
        for (int kk = 0; kk < BK; kk++) {
            float a[4], b[4];
#pragma unroll
            for (int i = 0; i < 4; i++) a[i] = As[kk][tr * 4 + i];
#pragma unroll
            for (int j = 0; j < 4; j++) b[j] = Bs[kk][tc * 4 + j];
#pragma unroll
            for (int i = 0; i < 4; i++)
#pragma unroll
                for (int j = 0; j < 4; j++)
                    acc[i][j] += a[i] * b[j];
        }
        __syncthreads();
    }

#pragma unroll
    for (int i = 0; i < 4; i++) {
        int gr = rowBase + tr * 4 + i;
        if (gr >= M) continue;
#pragma unroll
        for (int j = 0; j < 4; j++) {
            int gc = colBase + tc * 4 + j;
            float v = acc[i][j];
            if (bias) v += bias[gc];
            C[(size_t)gr * N + gc] = v;
        }
    }
}

// ---------------- launch ----------------
extern "C" void kernel_launch(void* const* d_in, const int* in_sizes, int n_in,
                              void* d_out, int out_size) {
    const float* x    = (const float*)d_in[0];
    const int*   hidx = (const int*)d_in[1];   // int32 on device (JAX x64 disabled)
    const float* W1   = (const float*)d_in[2];
    const float* b1   = (const float*)d_in[3];
    const float* W2   = (const float*)d_in[4];
    const float* b2   = (const float*)d_in[5];
    const float* Wp   = (const float*)d_in[6];
    const float* bp   = (const float*)d_in[7];

    int nnz = in_sizes[1] / 2;
    const int* node_idx = hidx;
    const int* edge_idx = hidx + nnz;

    // output layout: (z [N,64], features_1 [N,128], features_2 [N,64])
    float* z  = (float*)d_out;
    float* f1 = z  + (size_t)N_NODES * OUT_C;
    float* f2 = f1 + (size_t)N_NODES * HID_C;

    float *p_h0, *p_m, *p_h1, *p_dinv, *p_binv;
    int *p_ecnt, *p_ncnt, *p_eoff, *p_noff, *p_ecur, *p_ncur, *p_eadj, *p_nadj;
    cudaGetSymbolAddress((void**)&p_h0,   g_h0);
    cudaGetSymbolAddress((void**)&p_m,    g_m);
    cudaGetSymbolAddress((void**)&p_h1,   g_h1);
    cudaGetSymbolAddress((void**)&p_dinv, g_dinv);
    cudaGetSymbolAddress((void**)&p_binv, g_binv);
    cudaGetSymbolAddress((void**)&p_ecnt, g_ecnt);
    cudaGetSymbolAddress((void**)&p_ncnt, g_ncnt);
    cudaGetSymbolAddress((void**)&p_eoff, g_eoff);
    cudaGetSymbolAddress((void**)&p_noff, g_noff);
    cudaGetSymbolAddress((void**)&p_ecur, g_ecur);
    cudaGetSymbolAddress((void**)&p_ncur, g_ncur);
    cudaGetSymbolAddress((void**)&p_eadj, g_eadj);
    cudaGetSymbolAddress((void**)&p_nadj, g_nadj);

    // ---- CSR build ----
    cudaMemsetAsync(p_ecnt, 0, N_EDGES * sizeof(int));
    cudaMemsetAsync(p_ncnt, 0, N_NODES * sizeof(int));
    cudaMemsetAsync(p_ecur, 0, N_EDGES * sizeof(int));
    cudaMemsetAsync(p_ncur, 0, N_NODES * sizeof(int));
    hist_kernel<<<(nnz + 255) / 256, 256>>>(node_idx, edge_idx, p_ncnt, p_ecnt, nnz);
    scan_kernel<<<2, 1024>>>(p_ecnt, p_eoff, p_ncnt, p_noff, N_EDGES);
    invert_cnt_kernel<<<(N_NODES + 255) / 256, 256>>>(p_ncnt, p_dinv, p_ecnt, p_binv, N_NODES);
    fill_kernel<<<(nnz + 255) / 256, 256>>>(node_idx, edge_idx, p_eoff, p_noff,
                                            p_ecur, p_ncur, p_eadj, p_nadj, nnz);

    // ---- layer 1: h0 = x @ W1 ----
    {
        dim3 grid((N_NODES + 63) / 64, HID_C / 64);
        sgemm_kernel<<<grid, 256>>>(x, W1, p_h0, N_NODES, HID_C, IN_C, nullptr);
    }
    // node -> edge (C=128), then edge -> node fused with Dinv/bias/relu
    {
        int blocks = (N_EDGES * 32 + 255) / 256;
        agg_kernel<4, false, false><<<blocks, 256>>>(p_h0, p_eadj, p_eoff, nullptr,
                                                     p_m, nullptr, nullptr, N_EDGES);
        agg_kernel<4, true, true><<<blocks, 256>>>(p_m, p_nadj, p_noff, p_binv,
                                                   f1, p_dinv, b1, N_NODES);
    }

    // ---- layer 2: h1 = f1 @ W2 ----
    {
        dim3 grid((N_NODES + 63) / 64, OUT_C / 64);
        sgemm_kernel<<<grid, 256>>>(f1, W2, p_h1, N_NODES, OUT_C, HID_C, nullptr);
    }
    {
        int blocks = (N_EDGES * 32 + 255) / 256;
        agg_kernel<2, false, false><<<blocks, 256>>>(p_h1, p_eadj, p_eoff, nullptr,
                                                     p_m, nullptr, nullptr, N_EDGES);
        agg_kernel<2, true, true><<<blocks, 256>>>(p_m, p_nadj, p_noff, p_binv,
                                                   f2, p_dinv, b2, N_NODES);
    }

    // ---- projection: z = f2 @ Wp + bp ----
    {
        dim3 grid((N_NODES + 63) / 64, OUT_C / 64);
        sgemm_kernel<<<grid, 256>>>(f2, Wp, z, N_NODES, OUT_C, OUT_C, bp);
    }
}